// round 15
// baseline (speedup 1.0000x reference)
#include <cuda_runtime.h>
#include <cuda_bf16.h>

// ---------------------------------------------------------------------------
// SelfAttentionBlock: graph attention with per-edge RPE.
// N=50000, E=800000, DIM=256, H=16, D=8, DH=128, IN_RPE=18. SCALE=1/sqrt(8).
//
// Pipeline:
//   K0 init      : zero d_out, g_sum, g_cnt
//   K1a/K1b      : bf16-split converts (x, Wqkv)
//   S1 hist      : g_cnt[s]++ per edge
//   S2 scan      : exclusive prefix sum -> g_cur
//   S3 scatter   : counting-sort by s -> g_perm (edge id) + g_st (s,t pairs)
//   S4 permute   : g_eap[i*18..] = ea[perm[i]*18..]  (sorted-order edge attrs)
//   K1  gemm_mma : g_qkv = x @ Wqkv + bias via bf16x3 mma.sync
//   K2  compat   : SORTED walk, all streams coalesced (ea via g_eap, ex keyed
//                  by sorted position); q[s] L1-coherent; g_sum per-run acc
//   K3  message  : SORTED walk; streaming ex; ex*v reg-accumulated, RED/run
//   K4  normalize: out[i] /= (den[node,head] + eps)
// ---------------------------------------------------------------------------

#define MAX_N 50000
#define MAX_E 800000
#define HH    16
#define SCALE 0.35355339059327373f   // 8^-0.5

__device__ float g_qkv[(size_t)MAX_N * 512];   // [q(128) | k(128) | v(256)]
__device__ float g_ex [(size_t)MAX_E * HH];    // exp(compat), SORTED order
__device__ float g_sum[(size_t)MAX_N * HH];    // softmax denominators

// counting-sort scratch
__device__ int   g_cnt[MAX_N];
__device__ int   g_cur[MAX_N];
__device__ int   g_perm[MAX_E];
__device__ int2  g_st[MAX_E];                  // sorted (s, t) pairs
__device__ float g_eap[(size_t)MAX_E * 18];    // sorted edge attrs

// bf16-split scratch for the tensor-core GEMM
__device__ __nv_bfloat16 g_xh[(size_t)MAX_N * 256];
__device__ __nv_bfloat16 g_xl[(size_t)MAX_N * 256];
__device__ __nv_bfloat16 g_wht[512 * 256];     // transposed: [n][k]
__device__ __nv_bfloat16 g_wlt[512 * 256];

__device__ __forceinline__ void red_add_v4(float* addr, float a, float b,
                                           float c, float d) {
    asm volatile("red.global.v4.f32.add [%0], {%1, %2, %3, %4};"
                 :: "l"(addr), "f"(a), "f"(b), "f"(c), "f"(d)
                 : "memory");
}

__device__ __forceinline__ void cp_async_16(unsigned dst, const void* src,
                                            int srcBytes) {
    asm volatile("cp.async.cg.shared.global [%0], [%1], 16, %2;"
                 :: "r"(dst), "l"(src), "r"(srcBytes));
}

#define MMA16816(c, a0, a1, a2, a3, b0, b1)                                   \
    asm volatile("mma.sync.aligned.m16n8k16.row.col.f32.bf16.bf16.f32 "       \
                 "{%0,%1,%2,%3}, {%4,%5,%6,%7}, {%8,%9}, {%0,%1,%2,%3};"      \
                 : "+f"((c)[0]), "+f"((c)[1]), "+f"((c)[2]), "+f"((c)[3])     \
                 : "r"(a0), "r"(a1), "r"(a2), "r"(a3), "r"(b0), "r"(b1))

// --------------------------- K0: init --------------------------------------
__global__ void k_init(float4* __restrict__ out, int n_out4, int n_nodes) {
    int i = blockIdx.x * blockDim.x + threadIdx.x;
    if (i < n_out4) out[i] = make_float4(0.f, 0.f, 0.f, 0.f);
    if (i < n_nodes * HH) g_sum[i] = 0.0f;
    if (i < n_nodes) g_cnt[i] = 0;
}

// --------------------------- K1a: split-convert x ---------------------------
__global__ void k_convert_x(const float* __restrict__ x, int n) {
    int i = blockIdx.x * blockDim.x + threadIdx.x;
    if (i >= n) return;
    float v = x[i];
    __nv_bfloat16 h = __float2bfloat16(v);
    g_xh[i] = h;
    g_xl[i] = __float2bfloat16(v - __bfloat162float(h));
}

// --------------------------- K1b: split-convert + transpose W ---------------
__global__ void k_convert_w(const float* __restrict__ W) {
    int i = blockIdx.x * blockDim.x + threadIdx.x;   // i = k*512 + n
    if (i >= 256 * 512) return;
    int n = i & 511;
    int k = i >> 9;
    float v = W[i];
    __nv_bfloat16 h = __float2bfloat16(v);
    g_wht[n * 256 + k] = h;
    g_wlt[n * 256 + k] = __float2bfloat16(v - __bfloat162float(h));
}

// --------------------------- K1: bf16x3 tensor-core GEMM --------------------
#define SMSTRIDE 40
__global__ void __launch_bounds__(256) k_gemm_mma(
    const float* __restrict__ bias, int M)
{
    __shared__ __nv_bfloat16 Ah[128 * SMSTRIDE];
    __shared__ __nv_bfloat16 Al[128 * SMSTRIDE];
    __shared__ __nv_bfloat16 Bh[128 * SMSTRIDE];
    __shared__ __nv_bfloat16 Bl[128 * SMSTRIDE];

    const int tid  = threadIdx.x;
    const int wid  = tid >> 5;
    const int lane = tid & 31;
    const int g    = lane >> 2;
    const int tg   = lane & 3;
    const int wm   = wid >> 2;
    const int wn   = wid & 3;

    const int rowTile = blockIdx.y * 128;
    const int colTile = blockIdx.x * 128;

    const unsigned AhU = (unsigned)__cvta_generic_to_shared(Ah);
    const unsigned AlU = (unsigned)__cvta_generic_to_shared(Al);
    const unsigned BhU = (unsigned)__cvta_generic_to_shared(Bh);
    const unsigned BlU = (unsigned)__cvta_generic_to_shared(Bl);

    float acc[4][4][4];
#pragma unroll
    for (int mf = 0; mf < 4; mf++)
#pragma unroll
        for (int nf = 0; nf < 4; nf++)
#pragma unroll
            for (int r = 0; r < 4; r++) acc[mf][nf][r] = 0.0f;

#pragma unroll 1
    for (int kt = 0; kt < 8; kt++) {
        const int k0 = kt * 32;
#pragma unroll
        for (int j = 0; j < 2; j++) {
            int c   = tid + j * 256;
            int r   = c >> 2;
            int off = c & 3;
            unsigned soff = (unsigned)(r * SMSTRIDE * 2 + off * 16);

            int rowG = rowTile + r;
            int nb   = (rowG < M) ? 16 : 0;
            cp_async_16(AhU + soff, g_xh + (size_t)rowG * 256 + k0 + off * 8, nb);
            cp_async_16(AlU + soff, g_xl + (size_t)rowG * 256 + k0 + off * 8, nb);

            int nG = colTile + r;
            cp_async_16(BhU + soff, g_wht + (size_t)nG * 256 + k0 + off * 8, 16);
            cp_async_16(BlU + soff, g_wlt + (size_t)nG * 256 + k0 + off * 8, 16);
        }
        asm volatile("cp.async.commit_group;");
        asm volatile("cp.async.wait_group 0;");
        __syncthreads();

#pragma unroll
        for (int ks = 0; ks < 2; ks++) {
            const int kc = ks * 16 + tg * 2;

            unsigned bh[4][2], bl[4][2];
#pragma unroll
            for (int nf = 0; nf < 4; nf++) {
                int nb0 = (wn * 32 + nf * 8 + g) * SMSTRIDE;
                bh[nf][0] = *(const unsigned*)&Bh[nb0 + kc];
                bh[nf][1] = *(const unsigned*)&Bh[nb0 + kc + 8];
                bl[nf][0] = *(const unsigned*)&Bl[nb0 + kc];
                bl[nf][1] = *(const unsigned*)&Bl[nb0 + kc + 8];
            }
#pragma unroll
            for (int mf = 0; mf < 4; mf++) {
                int r0 = (wm * 64 + mf * 16 + g) * SMSTRIDE;
                int r8 = r0 + 8 * SMSTRIDE;
                unsigned ah0 = *(const unsigned*)&Ah[r0 + kc];
                unsigned ah1 = *(const unsigned*)&Ah[r8 + kc];
                unsigned ah2 = *(const unsigned*)&Ah[r0 + kc + 8];
                unsigned ah3 = *(const unsigned*)&Ah[r8 + kc + 8];
                unsigned al0 = *(const unsigned*)&Al[r0 + kc];
                unsigned al1 = *(const unsigned*)&Al[r8 + kc];
                unsigned al2 = *(const unsigned*)&Al[r0 + kc + 8];
                unsigned al3 = *(const unsigned*)&Al[r8 + kc + 8];
#pragma unroll
                for (int nf = 0; nf < 4; nf++) {
                    MMA16816(acc[mf][nf], ah0, ah1, ah2, ah3,
                             bh[nf][0], bh[nf][1]);
                    MMA16816(acc[mf][nf], ah0, ah1, ah2, ah3,
                             bl[nf][0], bl[nf][1]);
                    MMA16816(acc[mf][nf], al0, al1, al2, al3,
                             bh[nf][0], bh[nf][1]);
                }
            }
        }
        __syncthreads();
    }

#pragma unroll
    for (int mf = 0; mf < 4; mf++) {
        int row0 = rowTile + wm * 64 + mf * 16 + g;
        int row1 = row0 + 8;
#pragma unroll
        for (int nf = 0; nf < 4; nf++) {
            int col = colTile + wn * 32 + nf * 8 + tg * 2;
            float2 bb = *(const float2*)(bias + col);
            if (row0 < M) {
                float2 o = make_float2(acc[mf][nf][0] + bb.x,
                                       acc[mf][nf][1] + bb.y);
                *(float2*)(g_qkv + (size_t)row0 * 512 + col) = o;
            }
            if (row1 < M) {
                float2 o = make_float2(acc[mf][nf][2] + bb.x,
                                       acc[mf][nf][3] + bb.y);
                *(float2*)(g_qkv + (size_t)row1 * 512 + col) = o;
            }
        }
    }
}

// --------------------------- S1: histogram ----------------------------------
__global__ void k_hist(const int* __restrict__ ei, int E) {
    int i = blockIdx.x * blockDim.x + threadIdx.x;
    if (i < E) atomicAdd(&g_cnt[ei[i]], 1);
}

// --------------------------- S2: exclusive scan (single block) --------------
__global__ void __launch_bounds__(1024) k_scan(int n) {
    __shared__ int sh[1024];
    __shared__ int carry;
    int tid = threadIdx.x;
    if (tid == 0) carry = 0;
    __syncthreads();
    for (int base = 0; base < n; base += 1024) {
        int idx = base + tid;
        int v = (idx < n) ? g_cnt[idx] : 0;
        sh[tid] = v;
        __syncthreads();
#pragma unroll
        for (int off = 1; off < 1024; off <<= 1) {
            int t = (tid >= off) ? sh[tid - off] : 0;
            __syncthreads();
            sh[tid] += t;
            __syncthreads();
        }
        if (idx < n) g_cur[idx] = carry + sh[tid] - v;   // exclusive
        __syncthreads();
        if (tid == 1023) carry += sh[1023];
        __syncthreads();
    }
}

// --------------------------- S3: scatter (counting sort) --------------------
__global__ void k_scatter(const int* __restrict__ ei, int E) {
    int i = blockIdx.x * blockDim.x + threadIdx.x;
    if (i >= E) return;
    int s = ei[i];
    int t = ei[E + i];
    int pos = atomicAdd(&g_cur[s], 1);
    g_perm[pos] = i;
    g_st[pos] = make_int2(s, t);
}

// --------------------------- S4: permute edge attrs -------------------------
// g_eap[p*18 + j] = ea[perm[p]*18 + j]: random 72B reads, coalesced writes.
__global__ void k_permute_ea(const float* __restrict__ ea, int E) {
    int idx = blockIdx.x * blockDim.x + threadIdx.x;
    if (idx >= E * 18) return;
    int p = idx / 18;
    int j = idx - p * 18;
    g_eap[idx] = __ldg(ea + (size_t)g_perm[p] * 18 + j);
}

// --------------------------- K2: edge compat (sorted, streaming) ------------
// Warp-pairs walk contiguous chunks of the s-sorted edge list (parity owns a
// 64-dim half = 8 heads; lane owns 2 dims; 72 weight regs). All per-edge
// streams are coalesced: g_st, g_eap, g_ex (sorted-position keyed). Within a
// run q[s] hits L1 and the denominator accumulates in a register. The only
// random access left is the k[t] gather. 2-edge pipeline retained.
__global__ void __launch_bounds__(256, 2) k_edge_compat(
    const float* __restrict__ Wk, const float* __restrict__ bk,
    const float* __restrict__ Wq, const float* __restrict__ bq, int E)
{
    const int gwid   = (blockIdx.x * blockDim.x + threadIdx.x) >> 5;
    const int lane   = threadIdx.x & 31;
    const int parity = gwid & 1;
    const int c      = parity * 64 + lane * 2;

    float wq0[18], wq1[18], wk0[18], wk1[18];
#pragma unroll
    for (int i = 0; i < 18; i++) {
        float2 t = *(const float2*)(Wq + i * 128 + c);
        wq0[i] = t.x; wq1[i] = t.y;
        float2 u = *(const float2*)(Wk + i * 128 + c);
        wk0[i] = u.x; wk1[i] = u.y;
    }
    const float2 bqv = *(const float2*)(bq + c);
    const float2 bkv = *(const float2*)(bk + c);
    const int h = parity * 8 + (lane >> 2);

    const int nPairs = (gridDim.x * blockDim.x) >> 6;   // warp pairs
    const int wp     = gwid >> 1;
    const int per    = (E + nPairs - 1) / nPairs;
    const int start  = wp * per;
    const int end    = min(start + per, E);
    if (start >= end) return;

    float accs  = 0.0f;      // per-run denominator accumulator (lead lanes)
    int   cur_s = -1;

    for (int i = start; i < end; i += 2) {
        const int i1 = i + 1;
        const bool has1 = (i1 < end);
        const int i1c = has1 ? i1 : i;

        // ---- streaming loads + gathers, both edges ----
        int2 st0 = g_st[i];
        int2 st1 = g_st[i1c];

        float eal0 = (lane < 18) ? g_eap[(size_t)i   * 18 + lane] : 0.0f;
        float eal1 = (lane < 18) ? g_eap[(size_t)i1c * 18 + lane] : 0.0f;

        float2 q0 = *(const float2*)(g_qkv + (size_t)st0.x * 512 + c);
        float2 k0 = *(const float2*)(g_qkv + (size_t)st0.y * 512 + 128 + c);
        float2 q1 = *(const float2*)(g_qkv + (size_t)st1.x * 512 + c);
        float2 k1 = *(const float2*)(g_qkv + (size_t)st1.y * 512 + 128 + c);

        float aq0 = bqv.x, aq1 = bqv.y, ak0 = bkv.x, ak1 = bkv.y;
        float cq0 = bqv.x, cq1 = bqv.y, ck0 = bkv.x, ck1 = bkv.y;
#pragma unroll
        for (int j = 0; j < 18; j++) {
            float v0 = __shfl_sync(0xffffffffu, eal0, j);
            float v1 = __shfl_sync(0xffffffffu, eal1, j);
            aq0 += v0 * wq0[j]; aq1 += v0 * wq1[j];
            ak0 += v0 * wk0[j]; ak1 += v0 * wk1[j];
            cq0 += v1 * wq0[j]; cq1 += v1 * wq1[j];
            ck0 += v1 * wk0[j]; ck1 += v1 * wk1[j];
        }

        float p0 = (q0.x * SCALE + aq0) * (k0.x + ak0)
                 + (q0.y * SCALE + aq1) * (k0.y + ak1);
        p0 += __shfl_xor_sync(0xffffffffu, p0, 1);
        p0 += __shfl_xor_sync(0xffffffffu, p0, 2);

        float p1 = (q1.x * SCALE + cq0) * (k1.x + ck0)
                 + (q1.y * SCALE + cq1) * (k1.y + ck1);
        p1 += __shfl_xor_sync(0xffffffffu, p1, 1);
        p1 += __shfl_xor_sync(0xffffffffu, p1, 2);

        if ((lane & 3) == 0) {
            float ex0 = __expf(p0);        // safe: |compat| << 88
            g_ex[(size_t)i * HH + h] = ex0;     // sorted-position keyed
            if (st0.x != cur_s) {
                if (cur_s >= 0) atomicAdd(&g_sum[cur_s * HH + h], accs);
                cur_s = st0.x; accs = ex0;
            } else {
                accs += ex0;
            }
            if (has1) {
                float ex1 = __expf(p1);
                g_ex[(size_t)i1 * HH + h] = ex1;
                if (st1.x != cur_s) {
                    atomicAdd(&g_sum[cur_s * HH + h], accs);
                    cur_s = st1.x; accs = ex1;
                } else {
                    accs += ex1;
                }
            }
        }
    }
    if ((lane & 3) == 0 && cur_s >= 0)
        atomicAdd(&g_sum[cur_s * HH + h], accs);
}

// --------------------------- K3: message (sorted runs) ----------------------
// Warps walk contiguous chunks of the sorted edge list. Lane j owns out dims
// [8j, 8j+8) (head j/2). Streams: g_st, g_ex (sorted keyed). Random: v[t].
// ex*v reg-accumulates per run; flush = 2 red.global.v4 per run.
__global__ void __launch_bounds__(256) k_message_sorted(
    float* __restrict__ out, int E)
{
    const int gwid = (blockIdx.x * blockDim.x + threadIdx.x) >> 5;
    const int lane = threadIdx.x & 31;
    const int h    = lane >> 1;
    const int nW   = (gridDim.x * blockDim.x) >> 5;

    const int per   = (E + nW - 1) / nW;
    const int start = gwid * per;
    const int end   = min(start + per, E);
    if (start >= end) return;

    float4 acc0 = make_float4(0.f, 0.f, 0.f, 0.f);
    float4 acc1 = make_float4(0.f, 0.f, 0.f, 0.f);
    int cur_s = -1;

    for (int i = start; i < end; i++) {
        int2 st = g_st[i];
        float ex = g_ex[(size_t)i * HH + h];
        const float* vp = g_qkv + (size_t)st.y * 512 + 256 + lane * 8;
        float4 v0 = *(const float4*)vp;
        float4 v1 = *(const float4*)(vp + 4);

        if (st.x != cur_s) {
            if (cur_s >= 0) {
                float* op = out + (size_t)cur_s * 256 + lane * 8;
                red_add_v4(op,     acc0.x, acc0.y, acc0.z, acc0.w);
                red_add_v4(op + 4, acc1.x, acc1.y, acc1.z, acc1.w);
            }
            cur_s = st.x;
            acc0 = make_float4(0.f, 0.f, 0.f, 0.f);
            acc1 = make_float4(0.f, 0.f, 0.f, 0.f);
        }
        acc0.x += ex * v0.x; acc0.y += ex * v0.y;
        acc0.z += ex * v0.z; acc0.w += ex * v0.w;
        acc1.x += ex * v1.x; acc1.y += ex * v1.y;
        acc1.z += ex * v1.z; acc1.w += ex * v1.w;
    }
    if (cur_s >= 0) {
        float* op = out + (size_t)cur_s * 256 + lane * 8;
        red_add_v4(op,     acc0.x, acc0.y, acc0.z, acc0.w);
        red_add_v4(op + 4, acc1.x, acc1.y, acc1.z, acc1.w);
    }
}

// --------------------------- K4: normalize ----------------------------------
__global__ void k_normalize(float4* __restrict__ out, int n4) {
    int i = blockIdx.x * blockDim.x + threadIdx.x;
    if (i >= n4) return;
    int dim  = (i * 4) & 255;
    int node = i >> 6;
    float den = g_sum[node * HH + (dim >> 4)] + 1e-16f;
    float inv = 1.0f / den;
    float4 o = out[i];
    o.x *= inv; o.y *= inv; o.z *= inv; o.w *= inv;
    out[i] = o;
}

// ---------------------------------------------------------------------------
extern "C" void kernel_launch(void* const* d_in, const int* in_sizes, int n_in,
                              void* d_out, int out_size)
{
    const float* x    = (const float*)d_in[0];
    const int*   ei   = (const int*)d_in[1];
    const float* ea   = (const float*)d_in[2];
    const float* Wqkv = (const float*)d_in[3];
    const float* bqkv = (const float*)d_in[4];
    const float* Wk   = (const float*)d_in[5];
    const float* bk   = (const float*)d_in[6];
    const float* Wq   = (const float*)d_in[7];
    const float* bq   = (const float*)d_in[8];
    float*       out  = (float*)d_out;

    int M = in_sizes[0] / 256;   // num nodes
    int E = in_sizes[1] / 2;     // num edges

    int n_out4 = M * 64;
    k_init<<<(n_out4 + 255) / 256, 256>>>((float4*)out, n_out4, M);

    int nx = M * 256;
    k_convert_x<<<(nx + 255) / 256, 256>>>(x, nx);
    k_convert_w<<<(256 * 512 + 255) / 256, 256>>>(Wqkv);

    // Counting sort of edges by source node; carries (s,t) pairs.
    k_hist<<<(E + 255) / 256, 256>>>(ei, E);
    k_scan<<<1, 1024>>>(M);
    k_scatter<<<(E + 255) / 256, 256>>>(ei, E);
    k_permute_ea<<<(E * 18 + 255) / 256, 256>>>(ea, E);

    dim3 g1(4, (M + 127) / 128);
    k_gemm_mma<<<g1, 256>>>(bqkv, M);

    // Sorted compat: warp-pairs own contiguous chunks; all streams coalesced.
    k_edge_compat<<<1184, 256>>>(Wk, bk, Wq, bq, E);

    // Sorted message pass.
    k_message_sorted<<<1600, 256>>>(out, E);

    k_normalize<<<(n_out4 + 255) / 256, 256>>>((float4*)out, n_out4);
}

// round 16
// speedup vs baseline: 1.1578x; 1.1578x over previous
#include <cuda_runtime.h>
#include <cuda_bf16.h>

// ---------------------------------------------------------------------------
// SelfAttentionBlock: graph attention with per-edge RPE.
// N=50000, E=800000, DIM=256, H=16, D=8, DH=128, IN_RPE=18. SCALE=1/sqrt(8).
//
// Pipeline:
//   K0 init      : zero d_out, g_sum, g_cnt
//   K1a/K1b      : bf16-split converts (x, Wqkv)
//   S1 hist      : g_cnt[s]++ per edge
//   S2 scan1/2/3 : hierarchical exclusive prefix sum -> g_cur
//   S3 scatter   : counting-sort by s -> g_perm (edge id) + g_st (s,t pairs)
//   K1  gemm_mma : g_qkv = x @ Wqkv + bias, bf16x3 mma.sync, DOUBLE-BUFFERED
//   K2  compat   : SORTED walk; q[s] L1-coherent; g_sum per-run accumulator;
//                  g_ex keyed by sorted position
//   K3  message  : SORTED walk; ex*v reg-accumulated, RED per run
//   K4  normalize: out[i] /= (den[node,head] + eps)
// ---------------------------------------------------------------------------

#define MAX_N 50000
#define MAX_E 800000
#define HH    16
#define SCALE 0.35355339059327373f   // 8^-0.5

__device__ float g_qkv[(size_t)MAX_N * 512];   // [q(128) | k(128) | v(256)]
__device__ float g_ex [(size_t)MAX_E * HH];    // exp(compat), SORTED order
__device__ float g_sum[(size_t)MAX_N * HH];    // softmax denominators

// counting-sort scratch
__device__ int   g_cnt[MAX_N];
__device__ int   g_cur[MAX_N];
__device__ int   g_bsum[64];                   // scan block sums
__device__ int   g_perm[MAX_E];
__device__ int2  g_st[MAX_E];                  // sorted (s, t) pairs

// bf16-split scratch for the tensor-core GEMM
__device__ __nv_bfloat16 g_xh[(size_t)MAX_N * 256];
__device__ __nv_bfloat16 g_xl[(size_t)MAX_N * 256];
__device__ __nv_bfloat16 g_wht[512 * 256];     // transposed: [n][k]
__device__ __nv_bfloat16 g_wlt[512 * 256];

__device__ __forceinline__ void red_add_v4(float* addr, float a, float b,
                                           float c, float d) {
    asm volatile("red.global.v4.f32.add [%0], {%1, %2, %3, %4};"
                 :: "l"(addr), "f"(a), "f"(b), "f"(c), "f"(d)
                 : "memory");
}

__device__ __forceinline__ void cp_async_16(unsigned dst, const void* src,
                                            int srcBytes) {
    asm volatile("cp.async.cg.shared.global [%0], [%1], 16, %2;"
                 :: "r"(dst), "l"(src), "r"(srcBytes));
}

#define MMA16816(c, a0, a1, a2, a3, b0, b1)                                   \
    asm volatile("mma.sync.aligned.m16n8k16.row.col.f32.bf16.bf16.f32 "       \
                 "{%0,%1,%2,%3}, {%4,%5,%6,%7}, {%8,%9}, {%0,%1,%2,%3};"      \
                 : "+f"((c)[0]), "+f"((c)[1]), "+f"((c)[2]), "+f"((c)[3])     \
                 : "r"(a0), "r"(a1), "r"(a2), "r"(a3), "r"(b0), "r"(b1))

// --------------------------- K0: init --------------------------------------
__global__ void k_init(float4* __restrict__ out, int n_out4, int n_nodes) {
    int i = blockIdx.x * blockDim.x + threadIdx.x;
    if (i < n_out4) out[i] = make_float4(0.f, 0.f, 0.f, 0.f);
    if (i < n_nodes * HH) g_sum[i] = 0.0f;
    if (i < n_nodes) g_cnt[i] = 0;
}

// --------------------------- K1a: split-convert x ---------------------------
__global__ void k_convert_x(const float* __restrict__ x, int n) {
    int i = blockIdx.x * blockDim.x + threadIdx.x;
    if (i >= n) return;
    float v = x[i];
    __nv_bfloat16 h = __float2bfloat16(v);
    g_xh[i] = h;
    g_xl[i] = __float2bfloat16(v - __bfloat162float(h));
}

// --------------------------- K1b: split-convert + transpose W ---------------
__global__ void k_convert_w(const float* __restrict__ W) {
    int i = blockIdx.x * blockDim.x + threadIdx.x;   // i = k*512 + n
    if (i >= 256 * 512) return;
    int n = i & 511;
    int k = i >> 9;
    float v = W[i];
    __nv_bfloat16 h = __float2bfloat16(v);
    g_wht[n * 256 + k] = h;
    g_wlt[n * 256 + k] = __float2bfloat16(v - __bfloat162float(h));
}

// --------------------------- K1: bf16x3 GEMM, double-buffered ---------------
// C[M,512] = X[M,256] @ W[256,512] + bias, via Xh*Wh + Xh*Wl + Xl*Wh.
// CTA tile 128x128, K chunk 32, 8 warps, warp tile 64x32. Dynamic SMEM holds
// 2 buffers x 4 tiles; cp.async groups pipeline loads under MMA (wait_group 1).
#define SMSTRIDE 40
#define TILE_ELEMS (128 * SMSTRIDE)
__global__ void __launch_bounds__(256) k_gemm_mma(
    const float* __restrict__ bias, int M)
{
    extern __shared__ __nv_bfloat16 sm[];      // [2 bufs][Ah,Al,Bh,Bl]

    const int tid  = threadIdx.x;
    const int wid  = tid >> 5;
    const int lane = tid & 31;
    const int g    = lane >> 2;
    const int tg   = lane & 3;
    const int wm   = wid >> 2;
    const int wn   = wid & 3;

    const int rowTile = blockIdx.y * 128;
    const int colTile = blockIdx.x * 128;

    const unsigned smU = (unsigned)__cvta_generic_to_shared(sm);

    float acc[4][4][4];
#pragma unroll
    for (int mf = 0; mf < 4; mf++)
#pragma unroll
        for (int nf = 0; nf < 4; nf++)
#pragma unroll
            for (int r = 0; r < 4; r++) acc[mf][nf][r] = 0.0f;

    // --- stage one K-chunk into buffer `buf` ---
    auto load_tiles = [&](int buf, int kt) {
        const int k0 = kt * 32;
        const unsigned base = smU + (unsigned)(buf * 4 * TILE_ELEMS * 2);
#pragma unroll
        for (int j = 0; j < 2; j++) {
            int c   = tid + j * 256;
            int r   = c >> 2;
            int off = c & 3;
            unsigned soff = (unsigned)(r * SMSTRIDE * 2 + off * 16);
            int rowG = rowTile + r;
            int nb   = (rowG < M) ? 16 : 0;
            cp_async_16(base + 0 * TILE_ELEMS * 2 + soff,
                        g_xh + (size_t)rowG * 256 + k0 + off * 8, nb);
            cp_async_16(base + 1 * TILE_ELEMS * 2 + soff,
                        g_xl + (size_t)rowG * 256 + k0 + off * 8, nb);
            int nG = colTile + r;
            cp_async_16(base + 2 * TILE_ELEMS * 2 + soff,
                        g_wht + (size_t)nG * 256 + k0 + off * 8, 16);
            cp_async_16(base + 3 * TILE_ELEMS * 2 + soff,
                        g_wlt + (size_t)nG * 256 + k0 + off * 8, 16);
        }
        asm volatile("cp.async.commit_group;");
    };

    load_tiles(0, 0);

#pragma unroll 1
    for (int kt = 0; kt < 8; kt++) {
        if (kt < 7) {
            load_tiles((kt + 1) & 1, kt + 1);
            asm volatile("cp.async.wait_group 1;");   // cur buffer ready
        } else {
            asm volatile("cp.async.wait_group 0;");
        }
        __syncthreads();

        const __nv_bfloat16* Ah = sm + ((kt & 1) * 4 + 0) * TILE_ELEMS;
        const __nv_bfloat16* Al = sm + ((kt & 1) * 4 + 1) * TILE_ELEMS;
        const __nv_bfloat16* Bh = sm + ((kt & 1) * 4 + 2) * TILE_ELEMS;
        const __nv_bfloat16* Bl = sm + ((kt & 1) * 4 + 3) * TILE_ELEMS;

#pragma unroll
        for (int ks = 0; ks < 2; ks++) {
            const int kc = ks * 16 + tg * 2;

            unsigned bh[4][2], bl[4][2];
#pragma unroll
            for (int nf = 0; nf < 4; nf++) {
                int nb0 = (wn * 32 + nf * 8 + g) * SMSTRIDE;
                bh[nf][0] = *(const unsigned*)&Bh[nb0 + kc];
                bh[nf][1] = *(const unsigned*)&Bh[nb0 + kc + 8];
                bl[nf][0] = *(const unsigned*)&Bl[nb0 + kc];
                bl[nf][1] = *(const unsigned*)&Bl[nb0 + kc + 8];
            }
#pragma unroll
            for (int mf = 0; mf < 4; mf++) {
                int r0 = (wm * 64 + mf * 16 + g) * SMSTRIDE;
                int r8 = r0 + 8 * SMSTRIDE;
                unsigned ah0 = *(const unsigned*)&Ah[r0 + kc];
                unsigned ah1 = *(const unsigned*)&Ah[r8 + kc];
                unsigned ah2 = *(const unsigned*)&Ah[r0 + kc + 8];
                unsigned ah3 = *(const unsigned*)&Ah[r8 + kc + 8];
                unsigned al0 = *(const unsigned*)&Al[r0 + kc];
                unsigned al1 = *(const unsigned*)&Al[r8 + kc];
                unsigned al2 = *(const unsigned*)&Al[r0 + kc + 8];
                unsigned al3 = *(const unsigned*)&Al[r8 + kc + 8];
#pragma unroll
                for (int nf = 0; nf < 4; nf++) {
                    MMA16816(acc[mf][nf], ah0, ah1, ah2, ah3,
                             bh[nf][0], bh[nf][1]);
                    MMA16816(acc[mf][nf], ah0, ah1, ah2, ah3,
                             bl[nf][0], bl[nf][1]);
                    MMA16816(acc[mf][nf], al0, al1, al2, al3,
                             bh[nf][0], bh[nf][1]);
                }
            }
        }
        __syncthreads();   // next iter's cp.async overwrites this buffer
    }

#pragma unroll
    for (int mf = 0; mf < 4; mf++) {
        int row0 = rowTile + wm * 64 + mf * 16 + g;
        int row1 = row0 + 8;
#pragma unroll
        for (int nf = 0; nf < 4; nf++) {
            int col = colTile + wn * 32 + nf * 8 + tg * 2;
            float2 bb = *(const float2*)(bias + col);
            if (row0 < M) {
                float2 o = make_float2(acc[mf][nf][0] + bb.x,
                                       acc[mf][nf][1] + bb.y);
                *(float2*)(g_qkv + (size_t)row0 * 512 + col) = o;
            }
            if (row1 < M) {
                float2 o = make_float2(acc[mf][nf][2] + bb.x,
                                       acc[mf][nf][3] + bb.y);
                *(float2*)(g_qkv + (size_t)row1 * 512 + col) = o;
            }
        }
    }
}

// --------------------------- S1: histogram ----------------------------------
__global__ void k_hist(const int* __restrict__ ei, int E) {
    int i = blockIdx.x * blockDim.x + threadIdx.x;
    if (i < E) atomicAdd(&g_cnt[ei[i]], 1);
}

// --------------------------- S2: hierarchical exclusive scan ----------------
__global__ void __launch_bounds__(1024) k_scan1(int n) {   // grid = ceil(n/1024)
    __shared__ int sh[1024];
    int b = blockIdx.x, tid = threadIdx.x;
    int idx = b * 1024 + tid;
    int v = (idx < n) ? g_cnt[idx] : 0;
    sh[tid] = v;
    __syncthreads();
#pragma unroll
    for (int off = 1; off < 1024; off <<= 1) {
        int t = (tid >= off) ? sh[tid - off] : 0;
        __syncthreads();
        sh[tid] += t;
        __syncthreads();
    }
    if (idx < n) g_cur[idx] = sh[tid] - v;   // exclusive within block
    if (tid == 1023) g_bsum[b] = sh[1023];
}

__global__ void k_scan2(int nb) {   // 1 block, 64 threads (nb <= 64)
    __shared__ int sh[64];
    int tid = threadIdx.x;
    int v = (tid < nb) ? g_bsum[tid] : 0;
    sh[tid] = v;
    __syncthreads();
#pragma unroll
    for (int off = 1; off < 64; off <<= 1) {
        int t = (tid >= off) ? sh[tid - off] : 0;
        __syncthreads();
        sh[tid] += t;
        __syncthreads();
    }
    if (tid < nb) g_bsum[tid] = sh[tid] - v;   // exclusive block offsets
}

__global__ void k_scan3(int n) {
    int idx = blockIdx.x * blockDim.x + threadIdx.x;
    if (idx < n) g_cur[idx] += g_bsum[idx >> 10];
}

// --------------------------- S3: scatter (counting sort) --------------------
__global__ void k_scatter(const int* __restrict__ ei, int E) {
    int i = blockIdx.x * blockDim.x + threadIdx.x;
    if (i >= E) return;
    int s = ei[i];
    int t = ei[E + i];
    int pos = atomicAdd(&g_cur[s], 1);
    g_perm[pos] = i;
    g_st[pos] = make_int2(s, t);
}

// --------------------------- K2: edge compat (sorted walk) ------------------
// Warp-pairs walk contiguous chunks of the s-sorted edge list (parity owns a
// 64-dim half = 8 heads; lane owns 2 dims; 72 weight regs). q[s] hits L1
// within a run; denominator accumulates in a register (flush per run); g_ex
// keyed by sorted position (streaming writes). 2-edge pipeline.
__global__ void __launch_bounds__(256, 2) k_edge_compat(
    const float* __restrict__ ea,
    const float* __restrict__ Wk, const float* __restrict__ bk,
    const float* __restrict__ Wq, const float* __restrict__ bq, int E)
{
    const int gwid   = (blockIdx.x * blockDim.x + threadIdx.x) >> 5;
    const int lane   = threadIdx.x & 31;
    const int parity = gwid & 1;
    const int c      = parity * 64 + lane * 2;

    float wq0[18], wq1[18], wk0[18], wk1[18];
#pragma unroll
    for (int i = 0; i < 18; i++) {
        float2 t = *(const float2*)(Wq + i * 128 + c);
        wq0[i] = t.x; wq1[i] = t.y;
        float2 u = *(const float2*)(Wk + i * 128 + c);
        wk0[i] = u.x; wk1[i] = u.y;
    }
    const float2 bqv = *(const float2*)(bq + c);
    const float2 bkv = *(const float2*)(bk + c);
    const int h = parity * 8 + (lane >> 2);

    const int nPairs = (gridDim.x * blockDim.x) >> 6;
    const int wp     = gwid >> 1;
    const int per    = (E + nPairs - 1) / nPairs;
    const int start  = wp * per;
    const int end    = min(start + per, E);
    if (start >= end) return;

    float accs  = 0.0f;
    int   cur_s = -1;

    for (int i = start; i < end; i += 2) {
        const int i1 = i + 1;
        const bool has1 = (i1 < end);
        const int i1c = has1 ? i1 : i;

        int2 st0 = g_st[i];
        int2 st1 = g_st[i1c];
        int  e0  = g_perm[i];
        int  e1  = g_perm[i1c];

        float eal0 = (lane < 18) ? __ldg(ea + (size_t)e0 * 18 + lane) : 0.0f;
        float eal1 = (lane < 18) ? __ldg(ea + (size_t)e1 * 18 + lane) : 0.0f;

        float2 q0 = *(const float2*)(g_qkv + (size_t)st0.x * 512 + c);
        float2 k0 = *(const float2*)(g_qkv + (size_t)st0.y * 512 + 128 + c);
        float2 q1 = *(const float2*)(g_qkv + (size_t)st1.x * 512 + c);
        float2 k1 = *(const float2*)(g_qkv + (size_t)st1.y * 512 + 128 + c);

        float aq0 = bqv.x, aq1 = bqv.y, ak0 = bkv.x, ak1 = bkv.y;
        float cq0 = bqv.x, cq1 = bqv.y, ck0 = bkv.x, ck1 = bkv.y;
#pragma unroll
        for (int j = 0; j < 18; j++) {
            float v0 = __shfl_sync(0xffffffffu, eal0, j);
            float v1 = __shfl_sync(0xffffffffu, eal1, j);
            aq0 += v0 * wq0[j]; aq1 += v0 * wq1[j];
            ak0 += v0 * wk0[j]; ak1 += v0 * wk1[j];
            cq0 += v1 * wq0[j]; cq1 += v1 * wq1[j];
            ck0 += v1 * wk0[j]; ck1 += v1 * wk1[j];
        }

        float p0 = (q0.x * SCALE + aq0) * (k0.x + ak0)
                 + (q0.y * SCALE + aq1) * (k0.y + ak1);
        p0 += __shfl_xor_sync(0xffffffffu, p0, 1);
        p0 += __shfl_xor_sync(0xffffffffu, p0, 2);

        float p1 = (q1.x * SCALE + cq0) * (k1.x + ck0)
                 + (q1.y * SCALE + cq1) * (k1.y + ck1);
        p1 += __shfl_xor_sync(0xffffffffu, p1, 1);
        p1 += __shfl_xor_sync(0xffffffffu, p1, 2);

        if ((lane & 3) == 0) {
            float ex0 = __expf(p0);        // safe: |compat| << 88
            g_ex[(size_t)i * HH + h] = ex0;
            if (st0.x != cur_s) {
                if (cur_s >= 0) atomicAdd(&g_sum[cur_s * HH + h], accs);
                cur_s = st0.x; accs = ex0;
            } else {
                accs += ex0;
            }
            if (has1) {
                float ex1 = __expf(p1);
                g_ex[(size_t)i1 * HH + h] = ex1;
                if (st1.x != cur_s) {
                    atomicAdd(&g_sum[cur_s * HH + h], accs);
                    cur_s = st1.x; accs = ex1;
                } else {
                    accs += ex1;
                }
            }
        }
    }
    if ((lane & 3) == 0 && cur_s >= 0)
        atomicAdd(&g_sum[cur_s * HH + h], accs);
}

// --------------------------- K3: message (sorted runs) ----------------------
__global__ void __launch_bounds__(256) k_message_sorted(
    float* __restrict__ out, int E)
{
    const int gwid = (blockIdx.x * blockDim.x + threadIdx.x) >> 5;
    const int lane = threadIdx.x & 31;
    const int h    = lane >> 1;
    const int nW   = (gridDim.x * blockDim.x) >> 5;

    const int per   = (E + nW - 1) / nW;
    const int start = gwid * per;
    const int end   = min(start + per, E);
    if (start >= end) return;

    float4 acc0 = make_float4(0.f, 0.f, 0.f, 0.f);
    float4 acc1 = make_float4(0.f, 0.f, 0.f, 0.f);
    int cur_s = -1;

    for (int i = start; i < end; i++) {
        int2 st = g_st[i];
        float ex = g_ex[(size_t)i * HH + h];
        const float* vp = g_qkv + (size_t)st.y * 512 + 256 + lane * 8;
        float4 v0 = *(const float4*)vp;
        float4 v1 = *(const float4*)(vp + 4);

        if (st.x != cur_s) {
            if (cur_s >= 0) {
                float* op = out + (size_t)cur_s * 256 + lane * 8;
                red_add_v4(op,     acc0.x, acc0.y, acc0.z, acc0.w);
                red_add_v4(op + 4, acc1.x, acc1.y, acc1.z, acc1.w);
            }
            cur_s = st.x;
            acc0 = make_float4(0.f, 0.f, 0.f, 0.f);
            acc1 = make_float4(0.f, 0.f, 0.f, 0.f);
        }
        acc0.x += ex * v0.x; acc0.y += ex * v0.y;
        acc0.z += ex * v0.z; acc0.w += ex * v0.w;
        acc1.x += ex * v1.x; acc1.y += ex * v1.y;
        acc1.z += ex * v1.z; acc1.w += ex * v1.w;
    }
    if (cur_s >= 0) {
        float* op = out + (size_t)cur_s * 256 + lane * 8;
        red_add_v4(op,     acc0.x, acc0.y, acc0.z, acc0.w);
        red_add_v4(op + 4, acc1.x, acc1.y, acc1.z, acc1.w);
    }
}

// --------------------------- K4: normalize ----------------------------------
__global__ void k_normalize(float4* __restrict__ out, int n4) {
    int i = blockIdx.x * blockDim.x + threadIdx.x;
    if (i >= n4) return;
    int dim  = (i * 4) & 255;
    int node = i >> 6;
    float den = g_sum[node * HH + (dim >> 4)] + 1e-16f;
    float inv = 1.0f / den;
    float4 o = out[i];
    o.x *= inv; o.y *= inv; o.z *= inv; o.w *= inv;
    out[i] = o;
}

// ---------------------------------------------------------------------------
extern "C" void kernel_launch(void* const* d_in, const int* in_sizes, int n_in,
                              void* d_out, int out_size)
{
    const float* x    = (const float*)d_in[0];
    const int*   ei   = (const int*)d_in[1];
    const float* ea   = (const float*)d_in[2];
    const float* Wqkv = (const float*)d_in[3];
    const float* bqkv = (const float*)d_in[4];
    const float* Wk   = (const float*)d_in[5];
    const float* bk   = (const float*)d_in[6];
    const float* Wq   = (const float*)d_in[7];
    const float* bq   = (const float*)d_in[8];
    float*       out  = (float*)d_out;

    int M = in_sizes[0] / 256;   // num nodes
    int E = in_sizes[1] / 2;     // num edges

    int n_out4 = M * 64;
    k_init<<<(n_out4 + 255) / 256, 256>>>((float4*)out, n_out4, M);

    int nx = M * 256;
    k_convert_x<<<(nx + 255) / 256, 256>>>(x, nx);
    k_convert_w<<<(256 * 512 + 255) / 256, 256>>>(Wqkv);

    // Counting sort of edges by source node; carries (s,t) pairs.
    k_hist<<<(E + 255) / 256, 256>>>(ei, E);
    int nb = (M + 1023) / 1024;          // <= 64 for M <= 65536
    k_scan1<<<nb, 1024>>>(M);
    k_scan2<<<1, 64>>>(nb);
    k_scan3<<<(M + 255) / 256, 256>>>(M);
    k_scatter<<<(E + 255) / 256, 256>>>(ei, E);

    // Double-buffered GEMM: 2 x 4 tiles of 128x40 bf16 = 81920 B dynamic smem.
    int gemm_smem = 2 * 4 * TILE_ELEMS * 2;
    cudaFuncSetAttribute(k_gemm_mma,
                         cudaFuncAttributeMaxDynamicSharedMemorySize, gemm_smem);
    dim3 g1(4, (M + 127) / 128);
    k_gemm_mma<<<g1, 256, gemm_smem>>>(bqkv, M);

    // Sorted compat: warp-pairs own contiguous chunks.
    k_edge_compat<<<1184, 256>>>(ea, Wk, bk, Wq, bq, E);

    // Sorted message pass.
    k_message_sorted<<<1600, 256>>>(out, E);

    k_normalize<<<(n_out4 + 255) / 256, 256>>>((float4*)out, n_out4);
}

// round 17
// speedup vs baseline: 1.1724x; 1.0127x over previous
#include <cuda_runtime.h>
#include <cuda_bf16.h>

// ---------------------------------------------------------------------------
// SelfAttentionBlock: graph attention with per-edge RPE.
// N=50000, E=800000, DIM=256, H=16, D=8, DH=128, IN_RPE=18. SCALE=1/sqrt(8).
//
// Pipeline:
//   K0 init      : zero d_out, g_sum, g_cnt
//   K1a/K1b      : bf16-split converts (x, Wqkv)
//   S1 hist      : g_cnt[s]++ per edge
//   S2 scan1/2/3 : hierarchical exclusive prefix sum -> g_cur
//   S3 scatter   : counting-sort by s -> g_perm (edge id) + g_st (s,t pairs)
//   K1  gemm_mma : g_qkv = x @ Wqkv + bias, bf16x3 mma.sync, double-buffered;
//                  q columns pre-scaled by SCALE in the epilogue
//   K2  compat   : SORTED walk; RPE MACs via packed fma.rn.f32x2 (FFMA2);
//                  q[s] L1-coherent; per-run denominator accumulator
//   K3  message  : SORTED walk; ex*v reg-accumulated, RED per run
//   K4  normalize: out[i] /= (den[node,head] + eps)
// ---------------------------------------------------------------------------

#define MAX_N 50000
#define MAX_E 800000
#define HH    16
#define SCALE 0.35355339059327373f   // 8^-0.5

__device__ float g_qkv[(size_t)MAX_N * 512];   // [q*SCALE(128) | k(128) | v(256)]
__device__ float g_ex [(size_t)MAX_E * HH];    // exp(compat), SORTED order
__device__ float g_sum[(size_t)MAX_N * HH];    // softmax denominators

// counting-sort scratch (padded +2 for even-chunk paired loads)
__device__ int   g_cnt[MAX_N];
__device__ int   g_cur[MAX_N];
__device__ int   g_bsum[64];
__device__ int   g_perm[MAX_E + 2];
__device__ int2  g_st[MAX_E + 2];              // sorted (s, t) pairs

// bf16-split scratch for the tensor-core GEMM
__device__ __nv_bfloat16 g_xh[(size_t)MAX_N * 256];
__device__ __nv_bfloat16 g_xl[(size_t)MAX_N * 256];
__device__ __nv_bfloat16 g_wht[512 * 256];     // transposed: [n][k]
__device__ __nv_bfloat16 g_wlt[512 * 256];

__device__ __forceinline__ void red_add_v4(float* addr, float a, float b,
                                           float c, float d) {
    asm volatile("red.global.v4.f32.add [%0], {%1, %2, %3, %4};"
                 :: "l"(addr), "f"(a), "f"(b), "f"(c), "f"(d)
                 : "memory");
}

__device__ __forceinline__ void cp_async_16(unsigned dst, const void* src,
                                            int srcBytes) {
    asm volatile("cp.async.cg.shared.global [%0], [%1], 16, %2;"
                 :: "r"(dst), "l"(src), "r"(srcBytes));
}

// ---- packed fp32x2 helpers (sm_100+; ptxas never auto-emits FFMA2) ----
typedef unsigned long long ull;
__device__ __forceinline__ ull pack2(float x, float y) {
    ull r; asm("mov.b64 %0, {%1, %2};" : "=l"(r) : "f"(x), "f"(y)); return r;
}
__device__ __forceinline__ ull bcast2(float x) {
    ull r; asm("mov.b64 %0, {%1, %1};" : "=l"(r) : "f"(x)); return r;
}
__device__ __forceinline__ void unpack2(ull p, float& x, float& y) {
    asm("mov.b64 {%0, %1}, %2;" : "=f"(x), "=f"(y) : "l"(p));
}
__device__ __forceinline__ ull fma2(ull a, ull b, ull c) {
    ull d; asm("fma.rn.f32x2 %0, %1, %2, %3;"
               : "=l"(d) : "l"(a), "l"(b), "l"(c)); return d;
}

#define MMA16816(c, a0, a1, a2, a3, b0, b1)                                   \
    asm volatile("mma.sync.aligned.m16n8k16.row.col.f32.bf16.bf16.f32 "       \
                 "{%0,%1,%2,%3}, {%4,%5,%6,%7}, {%8,%9}, {%0,%1,%2,%3};"      \
                 : "+f"((c)[0]), "+f"((c)[1]), "+f"((c)[2]), "+f"((c)[3])     \
                 : "r"(a0), "r"(a1), "r"(a2), "r"(a3), "r"(b0), "r"(b1))

// --------------------------- K0: init --------------------------------------
__global__ void k_init(float4* __restrict__ out, int n_out4, int n_nodes) {
    int i = blockIdx.x * blockDim.x + threadIdx.x;
    if (i < n_out4) out[i] = make_float4(0.f, 0.f, 0.f, 0.f);
    if (i < n_nodes * HH) g_sum[i] = 0.0f;
    if (i < n_nodes) g_cnt[i] = 0;
}

// --------------------------- K1a: split-convert x ---------------------------
__global__ void k_convert_x(const float* __restrict__ x, int n) {
    int i = blockIdx.x * blockDim.x + threadIdx.x;
    if (i >= n) return;
    float v = x[i];
    __nv_bfloat16 h = __float2bfloat16(v);
    g_xh[i] = h;
    g_xl[i] = __float2bfloat16(v - __bfloat162float(h));
}

// --------------------------- K1b: split-convert + transpose W ---------------
__global__ void k_convert_w(const float* __restrict__ W) {
    int i = blockIdx.x * blockDim.x + threadIdx.x;   // i = k*512 + n
    if (i >= 256 * 512) return;
    int n = i & 511;
    int k = i >> 9;
    float v = W[i];
    __nv_bfloat16 h = __float2bfloat16(v);
    g_wht[n * 256 + k] = h;
    g_wlt[n * 256 + k] = __float2bfloat16(v - __bfloat162float(h));
}

// --------------------------- K1: bf16x3 GEMM, double-buffered ---------------
// q columns (colTile==0) are multiplied by SCALE in the epilogue so compat
// never needs the per-edge q*SCALE multiplies.
#define SMSTRIDE 40
#define TILE_ELEMS (128 * SMSTRIDE)
__global__ void __launch_bounds__(256) k_gemm_mma(
    const float* __restrict__ bias, int M)
{
    extern __shared__ __nv_bfloat16 sm[];      // [2 bufs][Ah,Al,Bh,Bl]

    const int tid  = threadIdx.x;
    const int wid  = tid >> 5;
    const int lane = tid & 31;
    const int g    = lane >> 2;
    const int tg   = lane & 3;
    const int wm   = wid >> 2;
    const int wn   = wid & 3;

    const int rowTile = blockIdx.y * 128;
    const int colTile = blockIdx.x * 128;
    const float cmul  = (colTile == 0) ? SCALE : 1.0f;

    const unsigned smU = (unsigned)__cvta_generic_to_shared(sm);

    float acc[4][4][4];
#pragma unroll
    for (int mf = 0; mf < 4; mf++)
#pragma unroll
        for (int nf = 0; nf < 4; nf++)
#pragma unroll
            for (int r = 0; r < 4; r++) acc[mf][nf][r] = 0.0f;

    auto load_tiles = [&](int buf, int kt) {
        const int k0 = kt * 32;
        const unsigned base = smU + (unsigned)(buf * 4 * TILE_ELEMS * 2);
#pragma unroll
        for (int j = 0; j < 2; j++) {
            int c   = tid + j * 256;
            int r   = c >> 2;
            int off = c & 3;
            unsigned soff = (unsigned)(r * SMSTRIDE * 2 + off * 16);
            int rowG = rowTile + r;
            int nb   = (rowG < M) ? 16 : 0;
            cp_async_16(base + 0 * TILE_ELEMS * 2 + soff,
                        g_xh + (size_t)rowG * 256 + k0 + off * 8, nb);
            cp_async_16(base + 1 * TILE_ELEMS * 2 + soff,
                        g_xl + (size_t)rowG * 256 + k0 + off * 8, nb);
            int nG = colTile + r;
            cp_async_16(base + 2 * TILE_ELEMS * 2 + soff,
                        g_wht + (size_t)nG * 256 + k0 + off * 8, 16);
            cp_async_16(base + 3 * TILE_ELEMS * 2 + soff,
                        g_wlt + (size_t)nG * 256 + k0 + off * 8, 16);
        }
        asm volatile("cp.async.commit_group;");
    };

    load_tiles(0, 0);

#pragma unroll 1
    for (int kt = 0; kt < 8; kt++) {
        if (kt < 7) {
            load_tiles((kt + 1) & 1, kt + 1);
            asm volatile("cp.async.wait_group 1;");
        } else {
            asm volatile("cp.async.wait_group 0;");
        }
        __syncthreads();

        const __nv_bfloat16* Ah = sm + ((kt & 1) * 4 + 0) * TILE_ELEMS;
        const __nv_bfloat16* Al = sm + ((kt & 1) * 4 + 1) * TILE_ELEMS;
        const __nv_bfloat16* Bh = sm + ((kt & 1) * 4 + 2) * TILE_ELEMS;
        const __nv_bfloat16* Bl = sm + ((kt & 1) * 4 + 3) * TILE_ELEMS;

#pragma unroll
        for (int ks = 0; ks < 2; ks++) {
            const int kc = ks * 16 + tg * 2;

            unsigned bh[4][2], bl[4][2];
#pragma unroll
            for (int nf = 0; nf < 4; nf++) {
                int nb0 = (wn * 32 + nf * 8 + g) * SMSTRIDE;
                bh[nf][0] = *(const unsigned*)&Bh[nb0 + kc];
                bh[nf][1] = *(const unsigned*)&Bh[nb0 + kc + 8];
                bl[nf][0] = *(const unsigned*)&Bl[nb0 + kc];
                bl[nf][1] = *(const unsigned*)&Bl[nb0 + kc + 8];
            }
#pragma unroll
            for (int mf = 0; mf < 4; mf++) {
                int r0 = (wm * 64 + mf * 16 + g) * SMSTRIDE;
                int r8 = r0 + 8 * SMSTRIDE;
                unsigned ah0 = *(const unsigned*)&Ah[r0 + kc];
                unsigned ah1 = *(const unsigned*)&Ah[r8 + kc];
                unsigned ah2 = *(const unsigned*)&Ah[r0 + kc + 8];
                unsigned ah3 = *(const unsigned*)&Ah[r8 + kc + 8];
                unsigned al0 = *(const unsigned*)&Al[r0 + kc];
                unsigned al1 = *(const unsigned*)&Al[r8 + kc];
                unsigned al2 = *(const unsigned*)&Al[r0 + kc + 8];
                unsigned al3 = *(const unsigned*)&Al[r8 + kc + 8];
#pragma unroll
                for (int nf = 0; nf < 4; nf++) {
                    MMA16816(acc[mf][nf], ah0, ah1, ah2, ah3,
                             bh[nf][0], bh[nf][1]);
                    MMA16816(acc[mf][nf], ah0, ah1, ah2, ah3,
                             bl[nf][0], bl[nf][1]);
                    MMA16816(acc[mf][nf], al0, al1, al2, al3,
                             bh[nf][0], bh[nf][1]);
                }
            }
        }
        __syncthreads();
    }

#pragma unroll
    for (int mf = 0; mf < 4; mf++) {
        int row0 = rowTile + wm * 64 + mf * 16 + g;
        int row1 = row0 + 8;
#pragma unroll
        for (int nf = 0; nf < 4; nf++) {
            int col = colTile + wn * 32 + nf * 8 + tg * 2;
            float2 bb = *(const float2*)(bias + col);
            if (row0 < M) {
                float2 o = make_float2((acc[mf][nf][0] + bb.x) * cmul,
                                       (acc[mf][nf][1] + bb.y) * cmul);
                *(float2*)(g_qkv + (size_t)row0 * 512 + col) = o;
            }
            if (row1 < M) {
                float2 o = make_float2((acc[mf][nf][2] + bb.x) * cmul,
                                       (acc[mf][nf][3] + bb.y) * cmul);
                *(float2*)(g_qkv + (size_t)row1 * 512 + col) = o;
            }
        }
    }
}

// --------------------------- S1: histogram ----------------------------------
__global__ void k_hist(const int* __restrict__ ei, int E) {
    int i = blockIdx.x * blockDim.x + threadIdx.x;
    if (i < E) atomicAdd(&g_cnt[ei[i]], 1);
}

// --------------------------- S2: hierarchical exclusive scan ----------------
__global__ void __launch_bounds__(1024) k_scan1(int n) {
    __shared__ int sh[1024];
    int b = blockIdx.x, tid = threadIdx.x;
    int idx = b * 1024 + tid;
    int v = (idx < n) ? g_cnt[idx] : 0;
    sh[tid] = v;
    __syncthreads();
#pragma unroll
    for (int off = 1; off < 1024; off <<= 1) {
        int t = (tid >= off) ? sh[tid - off] : 0;
        __syncthreads();
        sh[tid] += t;
        __syncthreads();
    }
    if (idx < n) g_cur[idx] = sh[tid] - v;
    if (tid == 1023) g_bsum[b] = sh[1023];
}

__global__ void k_scan2(int nb) {
    __shared__ int sh[64];
    int tid = threadIdx.x;
    int v = (tid < nb) ? g_bsum[tid] : 0;
    sh[tid] = v;
    __syncthreads();
#pragma unroll
    for (int off = 1; off < 64; off <<= 1) {
        int t = (tid >= off) ? sh[tid - off] : 0;
        __syncthreads();
        sh[tid] += t;
        __syncthreads();
    }
    if (tid < nb) g_bsum[tid] = sh[tid] - v;
}

__global__ void k_scan3(int n) {
    int idx = blockIdx.x * blockDim.x + threadIdx.x;
    if (idx < n) g_cur[idx] += g_bsum[idx >> 10];
}

// --------------------------- S3: scatter (counting sort) --------------------
__global__ void k_scatter(const int* __restrict__ ei, int E) {
    int i = blockIdx.x * blockDim.x + threadIdx.x;
    if (i >= E) return;
    int s = ei[i];
    int t = ei[E + i];
    int pos = atomicAdd(&g_cur[s], 1);
    g_perm[pos] = i;
    g_st[pos] = make_int2(s, t);
}

// --------------------------- K2: edge compat (sorted, FFMA2) ----------------
// Warp-pairs walk contiguous even-sized chunks of the s-sorted edge list.
// Parity owns a 64-dim half = 8 heads; lane owns a dim pair held as packed
// f32x2; RPE MACs use fma.rn.f32x2 (half the FMA-pipe ops of scalar FFMA).
// q is pre-scaled by SCALE in the GEMM. 2-edge pipeline; paired 16B g_st load.
__global__ void __launch_bounds__(256, 2) k_edge_compat(
    const float* __restrict__ ea,
    const float* __restrict__ Wk, const float* __restrict__ bk,
    const float* __restrict__ Wq, const float* __restrict__ bq, int E)
{
    const int gwid   = (blockIdx.x * blockDim.x + threadIdx.x) >> 5;
    const int lane   = threadIdx.x & 31;
    const int parity = gwid & 1;
    const int c      = parity * 64 + lane * 2;

    ull wqp[18], wkp[18];
#pragma unroll
    for (int i = 0; i < 18; i++) {
        float2 t = *(const float2*)(Wq + i * 128 + c);
        wqp[i] = pack2(t.x, t.y);
        float2 u = *(const float2*)(Wk + i * 128 + c);
        wkp[i] = pack2(u.x, u.y);
    }
    float2 tb = *(const float2*)(bq + c);
    const ull bqp = pack2(tb.x, tb.y);
    float2 ub = *(const float2*)(bk + c);
    const ull bkp = pack2(ub.x, ub.y);
    const int h = parity * 8 + (lane >> 2);

    const int nPairs = (gridDim.x * blockDim.x) >> 6;
    const int wp     = gwid >> 1;
    int per          = (E + nPairs - 1) / nPairs;
    per              = (per + 1) & ~1;            // even chunks: 16B st loads
    const int start  = wp * per;
    const int end    = min(start + per, E);
    if (start >= end) return;

    float accs  = 0.0f;
    int   cur_s = -1;

    for (int i = start; i < end; i += 2) {
        const int i1 = i + 1;
        const bool has1 = (i1 < end);

        // paired (s,t) load: one 16B transaction (i even, array padded)
        int4 stv = *(const int4*)&g_st[i];
        int2 st0 = make_int2(stv.x, stv.y);
        int2 st1 = has1 ? make_int2(stv.z, stv.w) : st0;
        int2 ep  = *(const int2*)&g_perm[i];
        int  e0  = ep.x;
        int  e1  = has1 ? ep.y : ep.x;

        float eal0 = (lane < 18) ? __ldg(ea + (size_t)e0 * 18 + lane) : 0.0f;
        float eal1 = (lane < 18) ? __ldg(ea + (size_t)e1 * 18 + lane) : 0.0f;

        float2 q0 = *(const float2*)(g_qkv + (size_t)st0.x * 512 + c);
        float2 k0 = *(const float2*)(g_qkv + (size_t)st0.y * 512 + 128 + c);
        float2 q1 = *(const float2*)(g_qkv + (size_t)st1.x * 512 + c);
        float2 k1 = *(const float2*)(g_qkv + (size_t)st1.y * 512 + 128 + c);

        ull aqp = bqp, akp = bkp, cqp = bqp, ckp = bkp;
#pragma unroll
        for (int j = 0; j < 18; j++) {
            ull v0p = bcast2(__shfl_sync(0xffffffffu, eal0, j));
            ull v1p = bcast2(__shfl_sync(0xffffffffu, eal1, j));
            aqp = fma2(wqp[j], v0p, aqp);
            akp = fma2(wkp[j], v0p, akp);
            cqp = fma2(wqp[j], v1p, cqp);
            ckp = fma2(wkp[j], v1p, ckp);
        }

        float aq0, aq1, ak0, ak1, cq0, cq1, ck0, ck1;
        unpack2(aqp, aq0, aq1);
        unpack2(akp, ak0, ak1);
        unpack2(cqp, cq0, cq1);
        unpack2(ckp, ck0, ck1);

        float p0 = (q0.x + aq0) * (k0.x + ak0)
                 + (q0.y + aq1) * (k0.y + ak1);
        p0 += __shfl_xor_sync(0xffffffffu, p0, 1);
        p0 += __shfl_xor_sync(0xffffffffu, p0, 2);

        float p1 = (q1.x + cq0) * (k1.x + ck0)
                 + (q1.y + cq1) * (k1.y + ck1);
        p1 += __shfl_xor_sync(0xffffffffu, p1, 1);
        p1 += __shfl_xor_sync(0xffffffffu, p1, 2);

        if ((lane & 3) == 0) {
            float ex0 = __expf(p0);        // safe: |compat| << 88
            g_ex[(size_t)i * HH + h] = ex0;
            if (st0.x != cur_s) {
                if (cur_s >= 0) atomicAdd(&g_sum[cur_s * HH + h], accs);
                cur_s = st0.x; accs = ex0;
            } else {
                accs += ex0;
            }
            if (has1) {
                float ex1 = __expf(p1);
                g_ex[(size_t)i1 * HH + h] = ex1;
                if (st1.x != cur_s) {
                    atomicAdd(&g_sum[cur_s * HH + h], accs);
                    cur_s = st1.x; accs = ex1;
                } else {
                    accs += ex1;
                }
            }
        }
    }
    if ((lane & 3) == 0 && cur_s >= 0)
        atomicAdd(&g_sum[cur_s * HH + h], accs);
}

// --------------------------- K3: message (sorted runs) ----------------------
__global__ void __launch_bounds__(256) k_message_sorted(
    float* __restrict__ out, int E)
{
    const int gwid = (blockIdx.x * blockDim.x + threadIdx.x) >> 5;
    const int lane = threadIdx.x & 31;
    const int h    = lane >> 1;
    const int nW   = (gridDim.x * blockDim.x) >> 5;

    const int per   = (E + nW - 1) / nW;
    const int start = gwid * per;
    const int end   = min(start + per, E);
    if (start >= end) return;

    float4 acc0 = make_float4(0.f, 0.f, 0.f, 0.f);
    float4 acc1 = make_float4(0.f, 0.f, 0.f, 0.f);
    int cur_s = -1;

    for (int i = start; i < end; i++) {
        int2 st = g_st[i];
        float ex = g_ex[(size_t)i * HH + h];
        const float* vp = g_qkv + (size_t)st.y * 512 + 256 + lane * 8;
        float4 v0 = *(const float4*)vp;
        float4 v1 = *(const float4*)(vp + 4);

        if (st.x != cur_s) {
            if (cur_s >= 0) {
                float* op = out + (size_t)cur_s * 256 + lane * 8;
                red_add_v4(op,     acc0.x, acc0.y, acc0.z, acc0.w);
                red_add_v4(op + 4, acc1.x, acc1.y, acc1.z, acc1.w);
            }
            cur_s = st.x;
            acc0 = make_float4(0.f, 0.f, 0.f, 0.f);
            acc1 = make_float4(0.f, 0.f, 0.f, 0.f);
        }
        acc0.x += ex * v0.x; acc0.y += ex * v0.y;
        acc0.z += ex * v0.z; acc0.w += ex * v0.w;
        acc1.x += ex * v1.x; acc1.y += ex * v1.y;
        acc1.z += ex * v1.z; acc1.w += ex * v1.w;
    }
    if (cur_s >= 0) {
        float* op = out + (size_t)cur_s * 256 + lane * 8;
        red_add_v4(op,     acc0.x, acc0.y, acc0.z, acc0.w);
        red_add_v4(op + 4, acc1.x, acc1.y, acc1.z, acc1.w);
    }
}

// --------------------------- K4: normalize ----------------------------------
__global__ void k_normalize(float4* __restrict__ out, int n4) {
    int i = blockIdx.x * blockDim.x + threadIdx.x;
    if (i >= n4) return;
    int dim  = (i * 4) & 255;
    int node = i >> 6;
    float den = g_sum[node * HH + (dim >> 4)] + 1e-16f;
    float inv = 1.0f / den;
    float4 o = out[i];
    o.x *= inv; o.y *= inv; o.z *= inv; o.w *= inv;
    out[i] = o;
}

// ---------------------------------------------------------------------------
extern "C" void kernel_launch(void* const* d_in, const int* in_sizes, int n_in,
                              void* d_out, int out_size)
{
    const float* x    = (const float*)d_in[0];
    const int*   ei   = (const int*)d_in[1];
    const float* ea   = (const float*)d_in[2];
    const float* Wqkv = (const float*)d_in[3];
    const float* bqkv = (const float*)d_in[4];
    const float* Wk   = (const float*)d_in[5];
    const float* bk   = (const float*)d_in[6];
    const float* Wq   = (const float*)d_in[7];
    const float* bq   = (const float*)d_in[8];
    float*       out  = (float*)d_out;

    int M = in_sizes[0] / 256;   // num nodes
    int E = in_sizes[1] / 2;     // num edges

    int n_out4 = M * 64;
    k_init<<<(n_out4 + 255) / 256, 256>>>((float4*)out, n_out4, M);

    int nx = M * 256;
    k_convert_x<<<(nx + 255) / 256, 256>>>(x, nx);
    k_convert_w<<<(256 * 512 + 255) / 256, 256>>>(Wqkv);

    // Counting sort of edges by source node; carries (s,t) pairs.
    k_hist<<<(E + 255) / 256, 256>>>(ei, E);
    int nb = (M + 1023) / 1024;
    k_scan1<<<nb, 1024>>>(M);
    k_scan2<<<1, 64>>>(nb);
    k_scan3<<<(M + 255) / 256, 256>>>(M);
    k_scatter<<<(E + 255) / 256, 256>>>(ei, E);

    // Double-buffered GEMM: 2 x 4 tiles of 128x40 bf16 = 81920 B dynamic smem.
    int gemm_smem = 2 * 4 * TILE_ELEMS * 2;
    cudaFuncSetAttribute(k_gemm_mma,
                         cudaFuncAttributeMaxDynamicSharedMemorySize, gemm_smem);
    dim3 g1(4, (M + 127) / 128);
    k_gemm_mma<<<g1, 256, gemm_smem>>>(bqkv, M);

    // Sorted compat (packed FFMA2).
    k_edge_compat<<<1184, 256>>>(ea, Wk, bk, Wq, bq, E);

    // Sorted message pass.
    k_message_sorted<<<1600, 256>>>(out, E);

    k_normalize<<<(n_out4 + 255) / 256, 256>>>((float4*)out, n_out4);
}